// round 11
// baseline (speedup 1.0000x reference)
#include <cuda_runtime.h>
#include <cstdint>
#include <math.h>

// Problem constants
#define BATCH   16
#define CC      16          // C
#define KK      8           // K
#define CK      128         // C*K
#define CIN     152         // C + C*K + K  (= 19 * 8)
#define HW      16384
#define PTILE   128
#define NTHREADS 1024
#define ASTRIDE 164         // A row stride; 164%32=4 -> GEMM A-frag banks 4g+tg (perm), 16B aligned
#define MUSTRIDE 132        // mu_s row stride (16B aligned)
#define WSIGSTRIDE 156      // 156%32=28 -> 28k distinct banks for k=0..7
#define SSTRIDE 132         // scratchA / pinew row stride: (4k+p) distinct banks

#define OUT_PI_OFF   0
#define OUT_MU_OFF   2097152
#define OUT_SIG_OFF  35651584
#define OUT_G_OFF    37748736

// Fragment-major weight layout: WF[chbIdx(4)][kb(19)][pair(2)][lane(32)][4]
#define WF_FLOATS (4*19*2*32*4)              // 19456

// Shared memory layout (float indices)
#define SM_A      0                          // A_s [128 px][164] tf32 = 20992 f
#define SM_W      20992                      // WF_s 19456 f (mu_s [128][132]=16896 overlay after GEMM)
#define SM_RHO    40448                      // rho plain [8][128]
#define SM_SCRA   41472                      // [8][132] alpha -> gamma contribs
#define SM_PINEW  42528                      // [8][132]
#define SM_WSIG   43584                      // [8][156]
#define SM_FLOATS 44832
#define SM_BYTES  (SM_FLOATS*4)              // 179328 B

__device__ float4 g_WF[WF_FLOATS/4];         // Wmu tf32 in fragment-major layout

__device__ __forceinline__ float to_tf32(float x) {
    uint32_t u;
    asm("cvt.rna.tf32.f32 %0, %1;" : "=r"(u) : "f"(x));
    return __uint_as_float(u);
}
__device__ __forceinline__ float sel4(float4 v, int i) {
    return i == 0 ? v.x : (i == 1 ? v.y : (i == 2 ? v.z : v.w));
}

// mma.sync m16n8k8 tf32 (base ISA, sm_80+)
__device__ __forceinline__ void mma_tf32(float* c, uint32_t a0, uint32_t a1, uint32_t a2, uint32_t a3,
                                         uint32_t b0, uint32_t b1) {
    asm volatile("mma.sync.aligned.m16n8k8.row.col.f32.tf32.tf32.f32 "
                 "{%0,%1,%2,%3}, {%4,%5,%6,%7}, {%8,%9}, {%0,%1,%2,%3};"
                 : "+f"(c[0]), "+f"(c[1]), "+f"(c[2]), "+f"(c[3])
                 : "r"(a0), "r"(a1), "r"(a2), "r"(a3), "r"(b0), "r"(b1));
}

// Prep: Wmu[o][k] -> fragment-major tf32
__global__ void prep_weights_kernel(const float* __restrict__ Wmu) {
    int idx = blockIdx.x * 256 + threadIdx.x;
    if (idx < CK * CIN) {
        int o = idx / CIN;
        int k = idx - o * CIN;
        int chbIdx = o >> 5, cho = o & 31, t = cho >> 3, g = cho & 7;
        int pair = t >> 1, th = t & 1;
        int kb = k >> 3, r = k & 7, tg = r & 3, bslot = r >> 2;
        int lane = g*4 + tg;
        int slot = th*2 + bslot;
        int fidx = ((((chbIdx*19 + kb)*2 + pair)*32 + lane)<<2) + slot;
        ((float*)g_WF)[fidx] = to_tf32(Wmu[idx]);
    }
}

__global__ __launch_bounds__(NTHREADS, 1)
void gmm_fused_kernel(const float* __restrict__ x,
                      const float* __restrict__ pi,
                      const float* __restrict__ mu,
                      const float* __restrict__ sigma,
                      const float* __restrict__ Wpi,
                      const float* __restrict__ bpi,
                      const float* __restrict__ bmu,
                      const float* __restrict__ Wsig,
                      const float* __restrict__ bsig,
                      const float* __restrict__ Wg,
                      const float* __restrict__ bg,
                      float* __restrict__ out)
{
    extern __shared__ float sm[];
    float* A_s      = sm + SM_A;
    float* WF_s     = sm + SM_W;
    float* rhopl    = sm + SM_RHO;
    float* scratchA = sm + SM_SCRA;
    float* pinew    = sm + SM_PINEW;
    float* wsig_s   = sm + SM_WSIG;

    const int tid   = threadIdx.x;
    const int wid   = tid >> 5;
    const int lane  = tid & 31;
    const int pix0  = blockIdx.x * PTILE;
    const int batch = pix0 >> 14;
    const int hw0   = pix0 & (HW - 1);

    const float* xb   = x     + batch*CC*HW + hw0;
    const float* pib  = pi    + batch*KK*HW + hw0;
    const float* mub  = mu    + batch*CK*HW + hw0;
    const float* sigb = sigma + batch*KK*HW + hw0;

    // ---------------- Staging: shuffle-transposed tf32 A tile ----------------
    // Per warp-iter: 4 channels x 32 pixels. lane -> q=lane>>2 (pixel quad), r=lane&3 (channel)
    {
        const int q = lane >> 2, r = lane & 3;
        for (int w = wid; w < (CC+CK)/4 * 4; w += 32) {   // 36*4 = 144 iters
            int ch0 = (w >> 2) * 4;
            int p0  = (w & 3) * 32;
            int c   = ch0 + r;
            const float* src = (c < CC) ? (xb + c*HW) : (mub + (c-CC)*HW);
            float4 v = *(const float4*)(src + p0 + q*4);
            v.x = to_tf32(v.x); v.y = to_tf32(v.y); v.z = to_tf32(v.z); v.w = to_tf32(v.w);
            // 4x4 transpose within quad
            float a1 = __shfl_xor_sync(0xFFFFFFFFu, sel4(v, r ^ 1), 1);
            float a2 = __shfl_xor_sync(0xFFFFFFFFu, sel4(v, r ^ 2), 2);
            float a3 = __shfl_xor_sync(0xFFFFFFFFu, sel4(v, r ^ 3), 3);
            float a0 = sel4(v, r);
            float4 wv;
            wv.x = (r==0) ? a0 : (r==1) ? a1 : (r==2) ? a2 : a3;
            wv.y = (r==0) ? a1 : (r==1) ? a0 : (r==2) ? a3 : a2;
            wv.z = (r==0) ? a2 : (r==1) ? a3 : (r==2) ? a0 : a1;
            wv.w = (r==0) ? a3 : (r==1) ? a2 : (r==2) ? a1 : a0;
            *(float4*)(A_s + (p0 + q*4 + r)*ASTRIDE + ch0) = wv;
        }
    }
    // WF_s: fragment-major weights, linear float4 copy
    {
        float4* dst = (float4*)WF_s;
        for (int i = tid; i < WF_FLOATS/4; i += NTHREADS)
            dst[i] = g_WF[i];
    }
    // wsig_s: stride-156 copy
    for (int idx = tid; idx < KK*CIN; idx += NTHREADS) {
        int k = idx / CIN;
        int i = idx - k*CIN;
        wsig_s[k*WSIGSTRIDE + i] = Wsig[idx];
    }
    __syncthreads();

    const float INV2PI = 0.15915494309189535f;

    // ---------------- Phase 0: dens, alpha, rho (p-major; coalesced LDG) ----------------
    {
        int t = tid;                 // k = t>>7, p = t&127
        int k = t >> 7;
        int p = t & 127;
        float s = sigb[k*HW + p];
        float invs2 = 1.0f / (s*s);
        float dist = 0.f;
        #pragma unroll
        for (int c = 0; c < CC; c++) {
            float d = xb[c*HW + p] - mub[(k*CC + c)*HW + p];
            dist = fmaf(d, d, dist);
        }
        float r  = invs2 * INV2PI;
        float r2 = r*r;
        float r4 = r2*r2;
        float dens = (r4*r4) * expf(-0.5f * dist * invs2);
        float piv  = pib[k*HW + p];
        float a    = piv * dens;
        float rho  = a * dens;
        scratchA[k*SSTRIDE + p] = a;
        rhopl[k*PTILE + p]      = rho;
        A_s[p*ASTRIDE + CC + CK + k] = to_tf32(rho);
    }
    __syncthreads();

    // ---------------- Phase 0b: pi logits ----------------
    {
        int t = tid;
        int k = t >> 7;
        int p = t & 127;
        float acc = bpi[k];
        #pragma unroll
        for (int j = 0; j < KK; j++)
            acc = fmaf(Wpi[k*2*KK + j], pib[j*HW + p], acc);
        #pragma unroll
        for (int j = 0; j < KK; j++)
            acc = fmaf(Wpi[k*2*KK + KK + j], scratchA[j*SSTRIDE + p], acc);
        pinew[k*SSTRIDE + p] = acc;
    }

    // ---------------- GEMM: tf32 mma.sync, fragment-major B ----------------
    const int g      = lane >> 2;       // 0..7
    const int tg     = lane & 3;        // 0..3
    const int pxt    = wid >> 2;        // 0..7   (16-pixel tile)
    const int chbIdx = wid & 3;         // 0..3   (32-channel block)
    const int chb    = chbIdx * 32;

    float acc[4][4];
    #pragma unroll
    for (int t = 0; t < 4; t++) {
        float b0v = bmu[chb + t*8 + 2*tg];
        float b1v = bmu[chb + t*8 + 2*tg + 1];
        acc[t][0] = b0v; acc[t][1] = b1v;
        acc[t][2] = b0v; acc[t][3] = b1v;
    }

    const float*  Abase = A_s + (pxt*16 + g)*ASTRIDE + tg;
    const float4* WFb   = (const float4*)WF_s + (chbIdx*19*2)*32 + lane;
    #pragma unroll
    for (int kb = 0; kb < CIN/8; kb++) {
        const int ko = kb * 8;
        uint32_t a0 = __float_as_uint(Abase[ko]);
        uint32_t a1 = __float_as_uint(Abase[8*ASTRIDE + ko]);
        uint32_t a2 = __float_as_uint(Abase[ko + 4]);
        uint32_t a3 = __float_as_uint(Abase[8*ASTRIDE + ko + 4]);
        float4 w0 = WFb[(kb*2 + 0)*32];
        float4 w1 = WFb[(kb*2 + 1)*32];
        mma_tf32(acc[0], a0, a1, a2, a3, __float_as_uint(w0.x), __float_as_uint(w0.y));
        mma_tf32(acc[1], a0, a1, a2, a3, __float_as_uint(w0.z), __float_as_uint(w0.w));
        mma_tf32(acc[2], a0, a1, a2, a3, __float_as_uint(w1.x), __float_as_uint(w1.y));
        mma_tf32(acc[3], a0, a1, a2, a3, __float_as_uint(w1.z), __float_as_uint(w1.w));
    }
    __syncthreads();   // all warps done reading WF_s / A_s; pinew written

    // ---------------- Epilogue: ReLU -> mu_s (overlay WF_s, stride 132) + softmax ----------------
    float* mu_s = WF_s;
    {
        int px = pxt*16 + g;
        #pragma unroll
        for (int t = 0; t < 4; t++) {
            int ch = chb + t*8 + 2*tg;
            float2 v0 = make_float2(fmaxf(acc[t][0], 0.f), fmaxf(acc[t][1], 0.f));
            float2 v1 = make_float2(fmaxf(acc[t][2], 0.f), fmaxf(acc[t][3], 0.f));
            *(float2*)(mu_s + px*MUSTRIDE + ch)     = v0;
            *(float2*)(mu_s + (px+8)*MUSTRIDE + ch) = v1;
        }
    }
    if (tid < PTILE) {
        int p = tid;
        float l[KK];
        float m = -1e30f;
        #pragma unroll
        for (int k = 0; k < KK; k++) { l[k] = pinew[k*SSTRIDE + p]; m = fmaxf(m, l[k]); }
        float ssum = 0.f;
        #pragma unroll
        for (int k = 0; k < KK; k++) { l[k] = expf(l[k] - m); ssum += l[k]; }
        float inv = 1.f / ssum;
        #pragma unroll
        for (int k = 0; k < KK; k++) {
            float v = l[k] * inv;
            pinew[k*SSTRIDE + p] = v;
            out[OUT_PI_OFF + batch*KK*HW + k*HW + hw0 + p] = v;
        }
    }
    __syncthreads();

    // Coalesced global store of mu_new
    for (int idx = tid; idx < CK*PTILE; idx += NTHREADS) {
        int ch = idx >> 7;
        int p  = idx & 127;
        out[OUT_MU_OFF + batch*CK*HW + ch*HW + hw0 + p] = mu_s[p*MUSTRIDE + ch];
    }

    // ---------------- Phase 2 (k-major): sigma conv + exp, dens2, gamma contribs ----------------
    {
        int t = tid;
        int p = t >> 3;              // 0..127 ; warp covers 4 pixels x 8 k
        int k = t & 7;
        const float* wk   = wsig_s + k*WSIGSTRIDE;
        const float* mrow = mu_s + p*MUSTRIDE;

        float a0 = bsig[k], a1 = 0.f, a2 = 0.f, a3 = 0.f;
        #pragma unroll
        for (int i = 0; i < CC; i += 4) {
            a0 = fmaf(wk[i],   xb[(i)*HW + p],   a0);
            a1 = fmaf(wk[i+1], xb[(i+1)*HW + p], a1);
            a2 = fmaf(wk[i+2], xb[(i+2)*HW + p], a2);
            a3 = fmaf(wk[i+3], xb[(i+3)*HW + p], a3);
        }
        #pragma unroll 8
        for (int i = 0; i < CK; i += 4) {
            float4 w4 = *(const float4*)(wk + CC + i);
            float4 m4 = *(const float4*)(mrow + i);
            a0 = fmaf(w4.x, m4.x, a0);
            a1 = fmaf(w4.y, m4.y, a1);
            a2 = fmaf(w4.z, m4.z, a2);
            a3 = fmaf(w4.w, m4.w, a3);
        }
        #pragma unroll
        for (int i = 0; i < KK; i += 4) {
            a0 = fmaf(wk[CC+CK+i],   rhopl[(i)*PTILE + p],   a0);
            a1 = fmaf(wk[CC+CK+i+1], rhopl[(i+1)*PTILE + p], a1);
            a2 = fmaf(wk[CC+CK+i+2], rhopl[(i+2)*PTILE + p], a2);
            a3 = fmaf(wk[CC+CK+i+3], rhopl[(i+3)*PTILE + p], a3);
        }
        float tval = fmaxf((a0 + a1) + (a2 + a3), 0.f);
        float snew = expf(tval);
        out[OUT_SIG_OFF + batch*KK*HW + k*HW + hw0 + p] = snew;

        float invs2 = 1.f / (snew*snew);
        float dist = 0.f;
        #pragma unroll
        for (int c4 = 0; c4 < 4; c4++) {
            float4 m4 = *(const float4*)(mrow + k*CC + c4*4);
            float d0 = xb[(c4*4+0)*HW + p] - m4.x;
            float d1 = xb[(c4*4+1)*HW + p] - m4.y;
            float d2 = xb[(c4*4+2)*HW + p] - m4.z;
            float d3 = xb[(c4*4+3)*HW + p] - m4.w;
            dist = fmaf(d0, d0, dist);
            dist = fmaf(d1, d1, dist);
            dist = fmaf(d2, d2, dist);
            dist = fmaf(d3, d3, dist);
        }
        float r  = invs2 * INV2PI;
        float r2 = r*r;
        float r4 = r2*r2;
        float dens2 = (r4*r4) * expf(-0.5f * dist * invs2);
        scratchA[k*SSTRIDE + p] = Wg[k] * pinew[k*SSTRIDE + p] * dens2;
    }
    __syncthreads();

    // ---------------- Phase 3: gamma ----------------
    if (tid < PTILE) {
        float gacc = bg[0];
        #pragma unroll
        for (int k = 0; k < KK; k++) gacc += scratchA[k*SSTRIDE + tid];
        out[OUT_G_OFF + batch*HW + hw0 + tid] = 1.f / (1.f + expf(-gacc));
    }
}

extern "C" void kernel_launch(void* const* d_in, const int* in_sizes, int n_in,
                              void* d_out, int out_size)
{
    const float* x     = (const float*)d_in[0];
    const float* pi    = (const float*)d_in[1];
    const float* mu    = (const float*)d_in[2];
    const float* sigma = (const float*)d_in[3];
    const float* Wpi   = (const float*)d_in[4];
    const float* bpi   = (const float*)d_in[5];
    const float* Wmu   = (const float*)d_in[6];
    const float* bmu   = (const float*)d_in[7];
    const float* Wsig  = (const float*)d_in[8];
    const float* bsig  = (const float*)d_in[9];
    const float* Wg    = (const float*)d_in[10];
    const float* bg    = (const float*)d_in[11];
    float* out = (float*)d_out;

    prep_weights_kernel<<<(CK*CIN + 255)/256, 256>>>(Wmu);

    cudaFuncSetAttribute(gmm_fused_kernel,
                         cudaFuncAttributeMaxDynamicSharedMemorySize, SM_BYTES);

    const int nblocks = (BATCH * HW) / PTILE;   // 2048
    gmm_fused_kernel<<<nblocks, NTHREADS, SM_BYTES>>>(
        x, pi, mu, sigma, Wpi, bpi, bmu, Wsig, bsig, Wg, bg, out);
}

// round 13
// speedup vs baseline: 1.0520x; 1.0520x over previous
#include <cuda_runtime.h>
#include <cstdint>
#include <math.h>

// Problem constants
#define BATCH   16
#define CC      16          // C
#define KK      8           // K
#define CK      128         // C*K
#define CIN     152         // C + C*K + K  (= 19 * 8)
#define HW      16384
#define PTILE   128
#define NTHREADS 1024
#define ASTRIDE 165         // A row stride (floats)
#define MUSTRIDE 132        // mu_s row stride (16B aligned)
#define WSIGSTRIDE 156      // 156%32=28 -> distinct banks for k=0..7
#define SSTRIDE 132         // scratchA / pinew row stride: (4k+p) bank permutation

#define OUT_PI_OFF   0
#define OUT_MU_OFF   2097152
#define OUT_SIG_OFF  35651584
#define OUT_G_OFF    37748736

// Fragment-major weight layout: WF[chbIdx(4)][kb(19)][pair(2)][lane(32)][4]
#define WF_FLOATS (4*19*2*32*4)              // 19456

// Shared memory layout (float indices)
#define SM_A      0                          // A_s [128 px][165] tf32 = 21120 f
#define SM_W      21120                      // WF_s 19456 f (mu_s [128][132]=16896 overlay after GEMM)
#define SM_XP     40576                      // x plain [16][128]
#define SM_RHO    42624                      // rho plain [8][128]
#define SM_SCRA   43648                      // [8][132] alpha -> gamma contribs
#define SM_PINEW  44704                      // [8][132]
#define SM_WSIG   45760                      // [8][156]
#define SM_FLOATS 47008
#define SM_BYTES  (SM_FLOATS*4)              // 188032 B

__device__ float4 g_WF[WF_FLOATS/4];         // Wmu tf32 in fragment-major layout

__device__ __forceinline__ float to_tf32(float x) {
    uint32_t u;
    asm("cvt.rna.tf32.f32 %0, %1;" : "=r"(u) : "f"(x));
    return __uint_as_float(u);
}

// mma.sync m16n8k8 tf32 (base ISA, sm_80+)
__device__ __forceinline__ void mma_tf32(float* c, uint32_t a0, uint32_t a1, uint32_t a2, uint32_t a3,
                                         uint32_t b0, uint32_t b1) {
    asm volatile("mma.sync.aligned.m16n8k8.row.col.f32.tf32.tf32.f32 "
                 "{%0,%1,%2,%3}, {%4,%5,%6,%7}, {%8,%9}, {%0,%1,%2,%3};"
                 : "+f"(c[0]), "+f"(c[1]), "+f"(c[2]), "+f"(c[3])
                 : "r"(a0), "r"(a1), "r"(a2), "r"(a3), "r"(b0), "r"(b1));
}

// Prep: Wmu[o][k] -> fragment-major tf32
__global__ void prep_weights_kernel(const float* __restrict__ Wmu) {
    int idx = blockIdx.x * 256 + threadIdx.x;
    if (idx < CK * CIN) {
        int o = idx / CIN;
        int k = idx - o * CIN;
        int chbIdx = o >> 5, cho = o & 31, t = cho >> 3, g = cho & 7;
        int pair = t >> 1, th = t & 1;
        int kb = k >> 3, r = k & 7, tg = r & 3, bslot = r >> 2;
        int lane = g*4 + tg;
        int slot = th*2 + bslot;
        int fidx = ((((chbIdx*19 + kb)*2 + pair)*32 + lane)<<2) + slot;
        ((float*)g_WF)[fidx] = to_tf32(Wmu[idx]);
    }
}

__global__ __launch_bounds__(NTHREADS, 1)
void gmm_fused_kernel(const float* __restrict__ x,
                      const float* __restrict__ pi,
                      const float* __restrict__ mu,
                      const float* __restrict__ sigma,
                      const float* __restrict__ Wpi,
                      const float* __restrict__ bpi,
                      const float* __restrict__ bmu,
                      const float* __restrict__ Wsig,
                      const float* __restrict__ bsig,
                      const float* __restrict__ Wg,
                      const float* __restrict__ bg,
                      float* __restrict__ out)
{
    extern __shared__ float sm[];
    float* A_s      = sm + SM_A;
    float* WF_s     = sm + SM_W;
    float* xplain   = sm + SM_XP;
    float* rhopl    = sm + SM_RHO;
    float* scratchA = sm + SM_SCRA;
    float* pinew    = sm + SM_PINEW;
    float* wsig_s   = sm + SM_WSIG;

    const int tid   = threadIdx.x;
    const int wid   = tid >> 5;
    const int lane  = tid & 31;
    const int pix0  = blockIdx.x * PTILE;
    const int batch = pix0 >> 14;
    const int hw0   = pix0 & (HW - 1);

    const float* xb   = x     + batch*CC*HW + hw0;
    const float* pib  = pi    + batch*KK*HW + hw0;
    const float* mub  = mu    + batch*CK*HW + hw0;
    const float* sigb = sigma + batch*KK*HW + hw0;

    // ---------------- Staging (float4 loads, scalar transposed stores) ----------------
    for (int idx = tid; idx < (CC+CK)*PTILE/4; idx += NTHREADS) {
        int c  = idx >> 5;
        int p4 = (idx & 31) << 2;
        float4 v = (c < CC) ? *(const float4*)(xb + c*HW + p4)
                            : *(const float4*)(mub + (c-CC)*HW + p4);
        A_s[(p4+0)*ASTRIDE + c] = to_tf32(v.x);
        A_s[(p4+1)*ASTRIDE + c] = to_tf32(v.y);
        A_s[(p4+2)*ASTRIDE + c] = to_tf32(v.z);
        A_s[(p4+3)*ASTRIDE + c] = to_tf32(v.w);
        if (c < CC) *(float4*)(xplain + c*PTILE + p4) = v;
    }
    // WF_s: fragment-major weights, linear float4 copy
    {
        float4* dst = (float4*)WF_s;
        for (int i = tid; i < WF_FLOATS/4; i += NTHREADS)
            dst[i] = g_WF[i];
    }
    // wsig_s: stride-156 copy
    for (int idx = tid; idx < KK*CIN; idx += NTHREADS) {
        int k = idx / CIN;
        int i = idx - k*CIN;
        wsig_s[k*WSIGSTRIDE + i] = Wsig[idx];
    }
    __syncthreads();

    const float INV2PI = 0.15915494309189535f;

    // ---------------- Phase 0: dens, alpha, rho (p-major, reads xplain) ----------------
    {
        int t = tid;                 // k = t>>7, p = t&127
        int k = t >> 7;
        int p = t & 127;
        float s = sigb[k*HW + p];
        float invs2 = 1.0f / (s*s);
        float dist = 0.f;
        #pragma unroll
        for (int c = 0; c < CC; c++) {
            float d = xplain[c*PTILE + p] - mub[(k*CC + c)*HW + p];
            dist = fmaf(d, d, dist);
        }
        float r  = invs2 * INV2PI;
        float r2 = r*r;
        float r4 = r2*r2;
        float dens = (r4*r4) * expf(-0.5f * dist * invs2);
        float piv  = pib[k*HW + p];
        float a    = piv * dens;
        float rho  = a * dens;
        scratchA[k*SSTRIDE + p] = a;
        rhopl[k*PTILE + p]      = rho;
        A_s[p*ASTRIDE + CC + CK + k] = to_tf32(rho);
    }
    __syncthreads();

    // ---------------- Phase 0b: pi logits ----------------
    {
        int t = tid;
        int k = t >> 7;
        int p = t & 127;
        float acc = bpi[k];
        #pragma unroll
        for (int j = 0; j < KK; j++)
            acc = fmaf(Wpi[k*2*KK + j], pib[j*HW + p], acc);
        #pragma unroll
        for (int j = 0; j < KK; j++)
            acc = fmaf(Wpi[k*2*KK + KK + j], scratchA[j*SSTRIDE + p], acc);
        pinew[k*SSTRIDE + p] = acc;
    }

    // ---------------- GEMM: tf32 mma.sync, fragment-major B ----------------
    const int g      = lane >> 2;       // 0..7
    const int tg     = lane & 3;        // 0..3
    const int pxt    = wid >> 2;        // 0..7   (16-pixel tile)
    const int chbIdx = wid & 3;         // 0..3   (32-channel block)
    const int chb    = chbIdx * 32;

    float acc[4][4];
    #pragma unroll
    for (int t = 0; t < 4; t++) {
        float b0v = bmu[chb + t*8 + 2*tg];
        float b1v = bmu[chb + t*8 + 2*tg + 1];
        acc[t][0] = b0v; acc[t][1] = b1v;
        acc[t][2] = b0v; acc[t][3] = b1v;
    }

    const float*  Abase = A_s + (pxt*16 + g)*ASTRIDE + tg;
    const float4* WFb   = (const float4*)WF_s + (chbIdx*19*2)*32 + lane;
    #pragma unroll
    for (int kb = 0; kb < CIN/8; kb++) {
        const int ko = kb * 8;
        uint32_t a0 = __float_as_uint(Abase[ko]);
        uint32_t a1 = __float_as_uint(Abase[8*ASTRIDE + ko]);
        uint32_t a2 = __float_as_uint(Abase[ko + 4]);
        uint32_t a3 = __float_as_uint(Abase[8*ASTRIDE + ko + 4]);
        float4 w0 = WFb[(kb*2 + 0)*32];
        float4 w1 = WFb[(kb*2 + 1)*32];
        mma_tf32(acc[0], a0, a1, a2, a3, __float_as_uint(w0.x), __float_as_uint(w0.y));
        mma_tf32(acc[1], a0, a1, a2, a3, __float_as_uint(w0.z), __float_as_uint(w0.w));
        mma_tf32(acc[2], a0, a1, a2, a3, __float_as_uint(w1.x), __float_as_uint(w1.y));
        mma_tf32(acc[3], a0, a1, a2, a3, __float_as_uint(w1.z), __float_as_uint(w1.w));
    }
    __syncthreads();   // all warps done reading WF_s / A_s; pinew written

    // ---------------- Epilogue: ReLU -> mu_s (overlay WF_s, stride 132) + softmax ----------------
    float* mu_s = WF_s;
    {
        int px = pxt*16 + g;
        #pragma unroll
        for (int t = 0; t < 4; t++) {
            int ch = chb + t*8 + 2*tg;
            float2 v0 = make_float2(fmaxf(acc[t][0], 0.f), fmaxf(acc[t][1], 0.f));
            float2 v1 = make_float2(fmaxf(acc[t][2], 0.f), fmaxf(acc[t][3], 0.f));
            *(float2*)(mu_s + px*MUSTRIDE + ch)     = v0;
            *(float2*)(mu_s + (px+8)*MUSTRIDE + ch) = v1;
        }
    }
    if (tid < PTILE) {
        int p = tid;
        float l[KK];
        float m = -1e30f;
        #pragma unroll
        for (int k = 0; k < KK; k++) { l[k] = pinew[k*SSTRIDE + p]; m = fmaxf(m, l[k]); }
        float ssum = 0.f;
        #pragma unroll
        for (int k = 0; k < KK; k++) { l[k] = expf(l[k] - m); ssum += l[k]; }
        float inv = 1.f / ssum;
        #pragma unroll
        for (int k = 0; k < KK; k++) {
            float v = l[k] * inv;
            pinew[k*SSTRIDE + p] = v;
            out[OUT_PI_OFF + batch*KK*HW + k*HW + hw0 + p] = v;
        }
    }
    __syncthreads();

    // Coalesced global store of mu_new
    for (int idx = tid; idx < CK*PTILE; idx += NTHREADS) {
        int ch = idx >> 7;
        int p  = idx & 127;
        out[OUT_MU_OFF + batch*CK*HW + ch*HW + hw0 + p] = mu_s[p*MUSTRIDE + ch];
    }

    // ---------------- Phase 2 (k-major): sigma conv + exp, dens2, gamma contribs ----------------
    {
        int t = tid;
        int p = t >> 3;              // warp covers 4 pixels x 8 k
        int k = t & 7;
        const float* wk   = wsig_s + k*WSIGSTRIDE;
        const float* mrow = mu_s + p*MUSTRIDE;

        float a0 = bsig[k], a1 = 0.f, a2 = 0.f, a3 = 0.f;
        #pragma unroll
        for (int i = 0; i < CC; i += 4) {
            a0 = fmaf(wk[i],   xplain[(i)*PTILE + p],   a0);
            a1 = fmaf(wk[i+1], xplain[(i+1)*PTILE + p], a1);
            a2 = fmaf(wk[i+2], xplain[(i+2)*PTILE + p], a2);
            a3 = fmaf(wk[i+3], xplain[(i+3)*PTILE + p], a3);
        }
        #pragma unroll 8
        for (int i = 0; i < CK; i += 4) {
            float4 w4 = *(const float4*)(wk + CC + i);
            float4 m4 = *(const float4*)(mrow + i);
            a0 = fmaf(w4.x, m4.x, a0);
            a1 = fmaf(w4.y, m4.y, a1);
            a2 = fmaf(w4.z, m4.z, a2);
            a3 = fmaf(w4.w, m4.w, a3);
        }
        #pragma unroll
        for (int i = 0; i < KK; i += 4) {
            a0 = fmaf(wk[CC+CK+i],   rhopl[(i)*PTILE + p],   a0);
            a1 = fmaf(wk[CC+CK+i+1], rhopl[(i+1)*PTILE + p], a1);
            a2 = fmaf(wk[CC+CK+i+2], rhopl[(i+2)*PTILE + p], a2);
            a3 = fmaf(wk[CC+CK+i+3], rhopl[(i+3)*PTILE + p], a3);
        }
        float tval = fmaxf((a0 + a1) + (a2 + a3), 0.f);
        float snew = expf(tval);
        out[OUT_SIG_OFF + batch*KK*HW + k*HW + hw0 + p] = snew;

        float invs2 = 1.f / (snew*snew);
        float dist = 0.f;
        #pragma unroll
        for (int c = 0; c < CC; c++) {
            float d = xplain[c*PTILE + p] - mrow[k*CC + c];
            dist = fmaf(d, d, dist);
        }
        float r  = invs2 * INV2PI;
        float r2 = r*r;
        float r4 = r2*r2;
        float dens2 = (r4*r4) * expf(-0.5f * dist * invs2);
        scratchA[k*SSTRIDE + p] = Wg[k] * pinew[k*SSTRIDE + p] * dens2;
    }
    __syncthreads();

    // ---------------- Phase 3: gamma ----------------
    if (tid < PTILE) {
        float gacc = bg[0];
        #pragma unroll
        for (int k = 0; k < KK; k++) gacc += scratchA[k*SSTRIDE + tid];
        out[OUT_G_OFF + batch*HW + hw0 + tid] = 1.f / (1.f + expf(-gacc));
    }
}

extern "C" void kernel_launch(void* const* d_in, const int* in_sizes, int n_in,
                              void* d_out, int out_size)
{
    const float* x     = (const float*)d_in[0];
    const float* pi    = (const float*)d_in[1];
    const float* mu    = (const float*)d_in[2];
    const float* sigma = (const float*)d_in[3];
    const float* Wpi   = (const float*)d_in[4];
    const float* bpi   = (const float*)d_in[5];
    const float* Wmu   = (const float*)d_in[6];
    const float* bmu   = (const float*)d_in[7];
    const float* Wsig  = (const float*)d_in[8];
    const float* bsig  = (const float*)d_in[9];
    const float* Wg    = (const float*)d_in[10];
    const float* bg    = (const float*)d_in[11];
    float* out = (float*)d_out;

    prep_weights_kernel<<<(CK*CIN + 255)/256, 256>>>(Wmu);

    cudaFuncSetAttribute(gmm_fused_kernel,
                         cudaFuncAttributeMaxDynamicSharedMemorySize, SM_BYTES);

    const int nblocks = (BATCH * HW) / PTILE;   // 2048
    gmm_fused_kernel<<<nblocks, NTHREADS, SM_BYTES>>>(
        x, pi, mu, sigma, Wpi, bpi, bmu, Wsig, bsig, Wg, bg, out);
}